// round 8
// baseline (speedup 1.0000x reference)
#include <cuda_runtime.h>
#include <cuda_bf16.h>
#include <cstdint>
#include <cfloat>

#define K_CODES 1024
#define DIM     256
#define T_LEN   4096
#define B_SZ    16
#define N_ROWS  65536
#define QN      ((size_t)16777216)
#define KSEG    768
#define NC_CH   8                       // 128-code chunks
#define KC_CH   24                      // 32-k chunks
#define CHUNKS  (NC_CH * KC_CH)         // 192
#define RSTRIDE 80                      // padded smem row stride (bytes)
#define TILE_B  (128 * RSTRIDE)         // 10240 per operand tile
#define STG     (2 * TILE_B)            // 20480 per stage
#define NSTAGE  3

__device__ __align__(256) __nv_bfloat16 g_A[(size_t)N_ROWS * KSEG];
__device__ __align__(256) __nv_bfloat16 g_Bm[(size_t)K_CODES * KSEG];
__device__ __align__(256) float g_enT[DIM * K_CODES];
__device__ float g_norm[N_ROWS];

__device__ __forceinline__ void cp16(uint32_t dst, const void* src) {
    asm volatile("cp.async.cg.shared.global [%0], [%1], 16;\n" :: "r"(dst), "l"(src));
}
__device__ __forceinline__ void cp_commit() { asm volatile("cp.async.commit_group;\n"); }
template <int N> __device__ __forceinline__ void cp_waitg() {
    asm volatile("cp.async.wait_group %0;\n" :: "n"(N));
}
__device__ __forceinline__ void ldsm4(uint32_t* r, uint32_t a) {
    asm volatile("ldmatrix.sync.aligned.m8n8.x4.shared.b16 {%0,%1,%2,%3}, [%4];"
                 : "=r"(r[0]), "=r"(r[1]), "=r"(r[2]), "=r"(r[3]) : "r"(a));
}
__device__ __forceinline__ void ldsm2(uint32_t* r, uint32_t a) {
    asm volatile("ldmatrix.sync.aligned.m8n8.x2.shared.b16 {%0,%1}, [%2];"
                 : "=r"(r[0]), "=r"(r[1]) : "r"(a));
}
__device__ __forceinline__ void mma16816(float* c, const uint32_t* a, const uint32_t* b) {
    asm volatile(
        "mma.sync.aligned.m16n8k16.row.col.f32.bf16.bf16.f32 "
        "{%0,%1,%2,%3},{%4,%5,%6,%7},{%8,%9},{%0,%1,%2,%3};"
        : "+f"(c[0]), "+f"(c[1]), "+f"(c[2]), "+f"(c[3])
        : "r"(a[0]), "r"(a[1]), "r"(a[2]), "r"(a[3]), "r"(b[0]), "r"(b[1]));
}

// --------- prep B: normalize embeddings -> g_enT, bf16 split -> g_Bm --------
__global__ void vq_prepB(const float* __restrict__ emb,
                         float* __restrict__ out, long long out_size) {
    int k = blockIdx.x, d = threadIdx.x;
    float v = emb[(size_t)k * DIM + d];
    float s = v * v;
    #pragma unroll
    for (int o = 16; o; o >>= 1) s += __shfl_xor_sync(0xFFFFFFFFu, s, o);
    __shared__ float ws[8]; __shared__ float rs_sh;
    if ((d & 31) == 0) ws[d >> 5] = s;
    __syncthreads();
    if (d == 0) {
        float t = 0.f;
        #pragma unroll
        for (int i = 0; i < 8; i++) t += ws[i];
        rs_sh = 1.0f / fmaxf(sqrtf(t), 1e-12f);
        if (k == 0 && out_size > (long long)QN) out[QN] = 0.0f;
    }
    __syncthreads();
    float en = v * rs_sh;
    g_enT[(size_t)d * K_CODES + k] = en;
    __nv_bfloat16 hi = __float2bfloat16(en);
    __nv_bfloat16 lo = __float2bfloat16(en - __bfloat162float(hi));
    __nv_bfloat16* row = g_Bm + (size_t)k * KSEG;
    row[d] = hi; row[256 + d] = lo; row[512 + d] = hi;   // [ehi|elo|ehi]
}

// --------- prep A: transpose x, bf16 split -> g_A [n][hi|hi|lo], norms ------
__global__ void vq_prepA(const float* __restrict__ x) {
    extern __shared__ float xs[];                 // [256][65]
    const int tid = threadIdx.x;
    const int b  = blockIdx.x >> 6;
    const int t0 = (blockIdx.x & 63) << 6;
    #pragma unroll
    for (int i = 0; i < 64; i++) {
        int lin = i * 256 + tid;
        int d = lin >> 6, tt = lin & 63;
        xs[d * 65 + tt] = x[((size_t)b * DIM + d) * T_LEN + t0 + tt];
    }
    __syncthreads();
    const int q = tid & 3, tt = tid >> 2;
    const int n = b * T_LEN + t0 + tt;
    __nv_bfloat16 hib[64], lob[64];
    float ss = 0.f;
    #pragma unroll
    for (int dd = 0; dd < 64; dd++) {
        float v = xs[(q * 64 + dd) * 65 + tt];
        ss = fmaf(v, v, ss);
        __nv_bfloat16 hi = __float2bfloat16(v);
        hib[dd] = hi;
        lob[dd] = __float2bfloat16(v - __bfloat162float(hi));
    }
    __nv_bfloat16* row = g_A + (size_t)n * KSEG;
    uint4* h4 = (uint4*)hib; uint4* l4 = (uint4*)lob;
    uint4* d0 = (uint4*)(row + q * 64);
    uint4* d1 = (uint4*)(row + 256 + q * 64);
    uint4* d2 = (uint4*)(row + 512 + q * 64);
    #pragma unroll
    for (int i = 0; i < 8; i++) { d0[i] = h4[i]; d1[i] = h4[i]; d2[i] = l4[i]; }
    ss += __shfl_xor_sync(0xFFFFFFFFu, ss, 1);
    ss += __shfl_xor_sync(0xFFFFFFFFu, ss, 2);
    if (q == 0) g_norm[n] = sqrtf(ss);
}

// --------- main: mma.sync GEMM + argmax + rescue + gather + loss ------------
__global__ void __launch_bounds__(256, 1) vq_main_kernel(
    const float* __restrict__ x, const float* __restrict__ emb,
    float* __restrict__ out, long long out_size)
{
    extern __shared__ char smem[];
    const uint32_t sb = (uint32_t)__cvta_generic_to_shared(smem);
    const int tid  = threadIdx.x;
    const int lane = tid & 31;
    const int wid  = tid >> 5;
    const int wm   = wid & 1;            // row half (64 rows)
    const int wn   = wid >> 1;           // 32-code group
    const int n0 = blockIdx.x * 128;
    const int b  = n0 >> 12;
    const int tl = n0 & 4095;

    auto load_chunk = [&](int s) {
        int nc = s / KC_CH, kc = s % KC_CH;
        uint32_t stg = sb + (uint32_t)(s % NSTAGE) * STG;
        const __nv_bfloat16* Asrc = g_A + (size_t)n0 * KSEG + kc * 32;
        #pragma unroll
        for (int i = 0; i < 2; i++) {
            int lin = i * 256 + tid;           // 0..511
            int row = lin >> 2, q = lin & 3;
            cp16(stg + (uint32_t)(row * RSTRIDE + q * 16),
                 Asrc + (size_t)row * KSEG + q * 8);
        }
        const __nv_bfloat16* Bsrc = g_Bm + (size_t)(nc * 128) * KSEG + kc * 32;
        #pragma unroll
        for (int i = 0; i < 2; i++) {
            int lin = i * 256 + tid;
            int row = lin >> 2, q = lin & 3;
            cp16(stg + TILE_B + (uint32_t)(row * RSTRIDE + q * 16),
                 Bsrc + (size_t)row * KSEG + q * 8);
        }
        cp_commit();
    };

    load_chunk(0); load_chunk(1);

    float acc[4][4][4];
    float rm1[8], rm2[8];
    int   ri1[8];
    #pragma unroll
    for (int i = 0; i < 8; i++) { rm1[i] = -FLT_MAX; rm2[i] = -FLT_MAX; ri1[i] = 0; }

    #pragma unroll 1
    for (int s = 0; s < CHUNKS; s++) {
        const int nc = s / KC_CH, kc = s % KC_CH;
        if (kc == 0) {
            #pragma unroll
            for (int mt = 0; mt < 4; mt++)
                #pragma unroll
                for (int nt = 0; nt < 4; nt++)
                    #pragma unroll
                    for (int c = 0; c < 4; c++) acc[mt][nt][c] = 0.f;
        }
        if (s < CHUNKS - 2)       cp_waitg<1>();
        else                      cp_waitg<0>();
        __syncthreads();                          // chunk s resident; prev compute done
        if (s + 2 < CHUNKS) load_chunk(s + 2);

        const uint32_t stg  = sb + (uint32_t)(s % NSTAGE) * STG;
        const uint32_t stgB = stg + TILE_B;
        #pragma unroll
        for (int ks = 0; ks < 2; ks++) {
            uint32_t af[4][4], bf[4][2];
            #pragma unroll
            for (int mt = 0; mt < 4; mt++) {
                int row = wm * 64 + mt * 16 + (lane & 15);
                ldsm4(af[mt], stg + (uint32_t)(row * RSTRIDE + ks * 32 + (lane >> 4) * 16));
            }
            #pragma unroll
            for (int nt = 0; nt < 4; nt++) {
                int rb = wn * 32 + nt * 8 + (lane & 7);
                ldsm2(bf[nt], stgB + (uint32_t)(rb * RSTRIDE + ks * 32 + ((lane >> 3) & 1) * 16));
            }
            #pragma unroll
            for (int mt = 0; mt < 4; mt++)
                #pragma unroll
                for (int nt = 0; nt < 4; nt++)
                    mma16816(acc[mt][nt], af[mt], bf[nt]);
        }

        if (kc == KC_CH - 1) {
            int cb = nc * 128 + wn * 32 + 2 * (lane & 3);
            #pragma unroll
            for (int mt = 0; mt < 4; mt++)
                #pragma unroll
                for (int nt = 0; nt < 4; nt++) {
                    int col = cb + nt * 8;
                    #pragma unroll
                    for (int c = 0; c < 4; c++) {
                        int slot = mt * 2 + (c >> 1);
                        int ci = col + (c & 1);
                        float v = acc[mt][nt][c];
                        if (v > rm1[slot]) { rm2[slot] = rm1[slot]; rm1[slot] = v; ri1[slot] = ci; }
                        else if (v > rm2[slot]) rm2[slot] = v;
                    }
                }
        }
    }
    __syncthreads();

    // ---- cross-partition top-2 reduce (reuse stage smem) ----
    float* redm1 = (float*)smem;                 // [128][16]
    int*   redix = (int*)(smem + 8192);          // [128][16]
    float* redm2 = (float*)(smem + 16384);       // [128][16]
    const int p = wn * 4 + (lane & 3);
    #pragma unroll
    for (int slot = 0; slot < 8; slot++) {
        int row = wm * 64 + (slot >> 1) * 16 + (slot & 1) * 8 + (lane >> 2);
        redm1[row * 16 + p] = rm1[slot];
        redix[row * 16 + p] = ri1[slot];
        redm2[row * 16 + p] = rm2[slot];
    }
    __syncthreads();

    int*   idx_s = (int*)(smem + 24576);         // [128]
    int*   rlist = idx_s + 128;                  // [128]
    int*   rcnt  = idx_s + 256;
    float* xrow  = (float*)(idx_s + 260);        // [256]
    float* rv    = xrow + 256;                   // [256]
    int*   rix   = (int*)(rv + 256);             // [256]

    if (tid == 0) *rcnt = 0;
    __syncthreads();
    if (tid < 128) {
        float g1 = -FLT_MAX, g2 = -FLT_MAX; int gi = 0;
        #pragma unroll 1
        for (int j = 0; j < 16; j++) {
            float m1 = redm1[tid * 16 + j];
            float m2 = redm2[tid * 16 + j];
            int   ix = redix[tid * 16 + j];
            if (m1 > g1) { g2 = fmaxf(fmaxf(g1, m2), g2); g1 = m1; gi = ix; }
            else         { g2 = fmaxf(g2, m1); }
        }
        idx_s[tid] = gi;
        if (g1 - g2 < 2e-4f * g_norm[n0 + tid]) {
            int q = atomicAdd(rcnt, 1); rlist[q] = tid;
        }
    }
    __syncthreads();

    // ---- exact fp32 rescue for tight-margin rows ----
    const int nr = *rcnt;
    #pragma unroll 1
    for (int e = 0; e < nr; e++) {
        const int rr = rlist[e];
        const int tt = (n0 + rr) & 4095;
        xrow[tid] = x[((size_t)b * DIM + tid) * T_LEN + tt];
        __syncthreads();
        float bv = -FLT_MAX; int bi = 0;
        #pragma unroll 1
        for (int cc = 0; cc < 4; cc++) {
            int c = cc * 256 + tid;
            float dot = 0.f;
            #pragma unroll 8
            for (int d = 0; d < 256; d++)
                dot = fmaf(xrow[d], g_enT[d * K_CODES + c], dot);
            if (dot > bv || (dot == bv && c < bi)) { bv = dot; bi = c; }
        }
        rv[tid] = bv; rix[tid] = bi;
        __syncthreads();
        if (tid == 0) {
            float best = rv[0]; int besti = rix[0];
            #pragma unroll 1
            for (int j = 1; j < 256; j++) {
                float v = rv[j]; int ix = rix[j];
                if (v > best || (v == best && ix < besti)) { best = v; besti = ix; }
            }
            idx_s[rr] = besti;
        }
        __syncthreads();
    }

    if (tid < 128 && out_size >= (long long)(QN + 1 + N_ROWS))
        out[QN + 1 + n0 + tid] = (float)idx_s[tid];

    // ---- gather + quantized write + exact loss ----
    const int r     = tid & 127;
    const int dhalf = tid >> 7;
    const int myidx = idx_s[r];
    const float4* erow4 = (const float4*)(emb + (size_t)myidx * DIM + dhalf * 128);
    const float* xb = x + ((size_t)b * DIM + dhalf * 128) * T_LEN + tl + r;
    float* ob = out + ((size_t)b * DIM + dhalf * 128) * T_LEN + tl + r;
    float lsum = 0.f;
    #pragma unroll 4
    for (int dj = 0; dj < 32; ++dj) {
        float4 e4 = erow4[dj];
        int d = dj * 4;
        float ev[4] = {e4.x, e4.y, e4.z, e4.w};
        #pragma unroll
        for (int i = 0; i < 4; i++) {
            float xv = xb[(size_t)(d + i) * T_LEN];
            float df = ev[i] - xv;
            lsum = fmaf(df, df, lsum);
            ob[(size_t)(d + i) * T_LEN] = ev[i];
        }
    }
    #pragma unroll
    for (int o = 16; o; o >>= 1) lsum += __shfl_xor_sync(0xFFFFFFFFu, lsum, o);
    __shared__ float wsum[8];
    if ((tid & 31) == 0) wsum[wid] = lsum;
    __syncthreads();
    if (tid == 0) {
        float t = 0.f;
        #pragma unroll
        for (int i = 0; i < 8; i++) t += wsum[i];
        if (out_size > (long long)QN)
            atomicAdd(out + QN, t * (1.25f / 16777216.0f));
    }
}

// ---------------------------------------------------------------------------
extern "C" void kernel_launch(void* const* d_in, const int* in_sizes, int n_in,
                              void* d_out, int out_size) {
    const float* x   = (const float*)d_in[0];
    const float* emb = (const float*)d_in[1];
    if (n_in >= 2 && in_sizes[0] == K_CODES * DIM && in_sizes[1] == (int)QN) {
        const float* t = x; x = emb; emb = t;
    }
    float* out = (float*)d_out;

    const int smemA = 256 * 65 * 4;                  // 66560
    const int smemM = NSTAGE * STG;                  // 61440
    cudaFuncSetAttribute(vq_prepA, cudaFuncAttributeMaxDynamicSharedMemorySize, smemA);
    cudaFuncSetAttribute(vq_main_kernel, cudaFuncAttributeMaxDynamicSharedMemorySize, smemM);

    vq_prepB<<<K_CODES, 256>>>(emb, out, (long long)out_size);
    vq_prepA<<<B_SZ * 64, 256, smemA>>>(x);
    vq_main_kernel<<<N_ROWS / 128, 256, smemM>>>(x, emb, out, (long long)out_size);
}

// round 9
// speedup vs baseline: 1.2834x; 1.2834x over previous
#include <cuda_runtime.h>
#include <cuda_bf16.h>
#include <cstdint>
#include <cfloat>

#define K_CODES 1024
#define DIM     256
#define T_LEN   4096
#define B_SZ    16
#define N_ROWS  65536
#define QN      ((size_t)16777216)
#define KSEG    768
#define NC_CH   8                       // 128-code chunks
#define KC_CH   12                      // 64-k chunks
#define CHUNKS  (NC_CH * KC_CH)         // 96
#define RSTRIDE 144                     // padded smem row stride (bytes), 64k*2B data
#define TILE_B  (128 * RSTRIDE)         // 18432 per operand tile
#define STG     (2 * TILE_B)            // 36864 per stage
#define NSTAGE  3
#define NTHR    512

__device__ __align__(256) __nv_bfloat16 g_A[(size_t)N_ROWS * KSEG];
__device__ __align__(256) __nv_bfloat16 g_Bm[(size_t)K_CODES * KSEG];
__device__ __align__(256) float g_enT[DIM * K_CODES];
__device__ float g_norm[N_ROWS];

__device__ __forceinline__ void cp16(uint32_t dst, const void* src) {
    asm volatile("cp.async.cg.shared.global [%0], [%1], 16;\n" :: "r"(dst), "l"(src));
}
__device__ __forceinline__ void cp_commit() { asm volatile("cp.async.commit_group;\n"); }
template <int N> __device__ __forceinline__ void cp_waitg() {
    asm volatile("cp.async.wait_group %0;\n" :: "n"(N));
}
__device__ __forceinline__ void ldsm4(uint32_t* r, uint32_t a) {
    asm volatile("ldmatrix.sync.aligned.m8n8.x4.shared.b16 {%0,%1,%2,%3}, [%4];"
                 : "=r"(r[0]), "=r"(r[1]), "=r"(r[2]), "=r"(r[3]) : "r"(a));
}
__device__ __forceinline__ void ldsm2(uint32_t* r, uint32_t a) {
    asm volatile("ldmatrix.sync.aligned.m8n8.x2.shared.b16 {%0,%1}, [%2];"
                 : "=r"(r[0]), "=r"(r[1]) : "r"(a));
}
__device__ __forceinline__ void mma16816(float* c, const uint32_t* a, const uint32_t* b) {
    asm volatile(
        "mma.sync.aligned.m16n8k16.row.col.f32.bf16.bf16.f32 "
        "{%0,%1,%2,%3},{%4,%5,%6,%7},{%8,%9},{%0,%1,%2,%3};"
        : "+f"(c[0]), "+f"(c[1]), "+f"(c[2]), "+f"(c[3])
        : "r"(a[0]), "r"(a[1]), "r"(a[2]), "r"(a[3]), "r"(b[0]), "r"(b[1]));
}

// --------- prep B: normalize embeddings -> g_enT, bf16 split -> g_Bm --------
__global__ void vq_prepB(const float* __restrict__ emb,
                         float* __restrict__ out, long long out_size) {
    int k = blockIdx.x, d = threadIdx.x;
    float v = emb[(size_t)k * DIM + d];
    float s = v * v;
    #pragma unroll
    for (int o = 16; o; o >>= 1) s += __shfl_xor_sync(0xFFFFFFFFu, s, o);
    __shared__ float ws[8]; __shared__ float rs_sh;
    if ((d & 31) == 0) ws[d >> 5] = s;
    __syncthreads();
    if (d == 0) {
        float t = 0.f;
        #pragma unroll
        for (int i = 0; i < 8; i++) t += ws[i];
        rs_sh = 1.0f / fmaxf(sqrtf(t), 1e-12f);
        if (k == 0 && out_size > (long long)QN) out[QN] = 0.0f;
    }
    __syncthreads();
    float en = v * rs_sh;
    g_enT[(size_t)d * K_CODES + k] = en;
    __nv_bfloat16 hi = __float2bfloat16(en);
    __nv_bfloat16 lo = __float2bfloat16(en - __bfloat162float(hi));
    __nv_bfloat16* row = g_Bm + (size_t)k * KSEG;
    row[d] = hi; row[256 + d] = lo; row[512 + d] = hi;   // [ehi|elo|ehi]
}

// --------- prep A: transpose x, bf16 split -> g_A [n][hi|hi|lo], norms ------
__global__ void vq_prepA(const float* __restrict__ x) {
    extern __shared__ float xs[];                 // [256][65]
    const int tid = threadIdx.x;
    const int b  = blockIdx.x >> 6;
    const int t0 = (blockIdx.x & 63) << 6;
    #pragma unroll
    for (int i = 0; i < 64; i++) {
        int lin = i * 256 + tid;
        int d = lin >> 6, tt = lin & 63;
        xs[d * 65 + tt] = x[((size_t)b * DIM + d) * T_LEN + t0 + tt];
    }
    __syncthreads();
    const int q = tid & 3, tt = tid >> 2;
    const int n = b * T_LEN + t0 + tt;
    __nv_bfloat16 hib[64], lob[64];
    float ss = 0.f;
    #pragma unroll
    for (int dd = 0; dd < 64; dd++) {
        float v = xs[(q * 64 + dd) * 65 + tt];
        ss = fmaf(v, v, ss);
        __nv_bfloat16 hi = __float2bfloat16(v);
        hib[dd] = hi;
        lob[dd] = __float2bfloat16(v - __bfloat162float(hi));
    }
    __nv_bfloat16* row = g_A + (size_t)n * KSEG;
    uint4* h4 = (uint4*)hib; uint4* l4 = (uint4*)lob;
    uint4* d0 = (uint4*)(row + q * 64);
    uint4* d1 = (uint4*)(row + 256 + q * 64);
    uint4* d2 = (uint4*)(row + 512 + q * 64);
    #pragma unroll
    for (int i = 0; i < 8; i++) { d0[i] = h4[i]; d1[i] = h4[i]; d2[i] = l4[i]; }
    ss += __shfl_xor_sync(0xFFFFFFFFu, ss, 1);
    ss += __shfl_xor_sync(0xFFFFFFFFu, ss, 2);
    if (q == 0) g_norm[n] = sqrtf(ss);
}

// --------- main: mma.sync GEMM (16 warps) + argmax + rescue + epilogue ------
__global__ void __launch_bounds__(NTHR, 1) vq_main_kernel(
    const float* __restrict__ x, const float* __restrict__ emb,
    float* __restrict__ out, long long out_size)
{
    extern __shared__ char smem[];
    const uint32_t sb = (uint32_t)__cvta_generic_to_shared(smem);
    const int tid  = threadIdx.x;
    const int lane = tid & 31;
    const int wid  = tid >> 5;
    const int wm   = wid & 3;            // 32-row group
    const int wn   = wid >> 2;           // 32-code group
    const int n0 = blockIdx.x * 128;
    const int b  = n0 >> 12;
    const int tl = n0 & 4095;

    auto load_chunk = [&](int s) {
        int nc = s / KC_CH, kc = s % KC_CH;
        uint32_t stg = sb + (uint32_t)(s % NSTAGE) * STG;
        const __nv_bfloat16* Asrc = g_A + (size_t)n0 * KSEG + kc * 64;
        #pragma unroll
        for (int i = 0; i < 2; i++) {
            int lin = i * NTHR + tid;          // 0..1023
            int row = lin >> 3, q = lin & 7;
            cp16(stg + (uint32_t)(row * RSTRIDE + q * 16),
                 Asrc + (size_t)row * KSEG + q * 8);
        }
        const __nv_bfloat16* Bsrc = g_Bm + (size_t)(nc * 128) * KSEG + kc * 64;
        #pragma unroll
        for (int i = 0; i < 2; i++) {
            int lin = i * NTHR + tid;
            int row = lin >> 3, q = lin & 7;
            cp16(stg + TILE_B + (uint32_t)(row * RSTRIDE + q * 16),
                 Bsrc + (size_t)row * KSEG + q * 8);
        }
        cp_commit();
    };

    load_chunk(0); load_chunk(1);

    float acc[2][4][4];
    float rm1[4], rm2[4];
    int   ri1[4];
    #pragma unroll
    for (int i = 0; i < 4; i++) { rm1[i] = -FLT_MAX; rm2[i] = -FLT_MAX; ri1[i] = 0; }

    #pragma unroll 1
    for (int s = 0; s < CHUNKS; s++) {
        const int nc = s / KC_CH, kc = s % KC_CH;
        if (kc == 0) {
            #pragma unroll
            for (int mt = 0; mt < 2; mt++)
                #pragma unroll
                for (int nt = 0; nt < 4; nt++)
                    #pragma unroll
                    for (int c = 0; c < 4; c++) acc[mt][nt][c] = 0.f;
        }
        if (s < CHUNKS - 2) cp_waitg<1>(); else cp_waitg<0>();
        __syncthreads();                          // chunk s resident; prev compute done
        if (s + 2 < CHUNKS) load_chunk(s + 2);

        const uint32_t stg  = sb + (uint32_t)(s % NSTAGE) * STG;
        const uint32_t stgB = stg + TILE_B;
        #pragma unroll
        for (int ks = 0; ks < 4; ks++) {
            uint32_t af[2][4], bf[4][2];
            #pragma unroll
            for (int mt = 0; mt < 2; mt++) {
                int row = wm * 32 + mt * 16 + (lane & 15);
                ldsm4(af[mt], stg + (uint32_t)(row * RSTRIDE + ks * 32 + (lane >> 4) * 16));
            }
            #pragma unroll
            for (int nt = 0; nt < 4; nt++) {
                int rb = wn * 32 + nt * 8 + (lane & 7);
                ldsm2(bf[nt], stgB + (uint32_t)(rb * RSTRIDE + ks * 32 + ((lane >> 3) & 1) * 16));
            }
            #pragma unroll
            for (int mt = 0; mt < 2; mt++)
                #pragma unroll
                for (int nt = 0; nt < 4; nt++)
                    mma16816(acc[mt][nt], af[mt], bf[nt]);
        }

        if (kc == KC_CH - 1) {
            int cb = nc * 128 + wn * 32 + 2 * (lane & 3);
            #pragma unroll
            for (int mt = 0; mt < 2; mt++)
                #pragma unroll
                for (int nt = 0; nt < 4; nt++) {
                    int col = cb + nt * 8;
                    #pragma unroll
                    for (int c = 0; c < 4; c++) {
                        int slot = mt * 2 + (c >> 1);
                        int ci = col + (c & 1);
                        float v = acc[mt][nt][c];
                        if (v > rm1[slot]) { rm2[slot] = rm1[slot]; rm1[slot] = v; ri1[slot] = ci; }
                        else if (v > rm2[slot]) rm2[slot] = v;
                    }
                }
        }
    }
    __syncthreads();

    // ---- cross-partition top-2 reduce (reuse stage smem) ----
    float* redm1 = (float*)smem;                 // [128][16]
    int*   redix = (int*)(smem + 8192);          // [128][16]
    float* redm2 = (float*)(smem + 16384);       // [128][16]
    const int p = wn * 4 + (lane & 3);
    #pragma unroll
    for (int slot = 0; slot < 4; slot++) {
        int row = wm * 32 + (slot >> 1) * 16 + (slot & 1) * 8 + (lane >> 2);
        redm1[row * 16 + p] = rm1[slot];
        redix[row * 16 + p] = ri1[slot];
        redm2[row * 16 + p] = rm2[slot];
    }
    __syncthreads();

    int*   idx_s = (int*)(smem + 24576);         // [128]
    int*   rlist = idx_s + 128;                  // [128]
    int*   rcnt  = idx_s + 256;
    float* xrow  = (float*)(idx_s + 260);        // [256]
    float* rv    = xrow + 256;                   // [512]
    int*   rix   = (int*)(rv + 512);             // [512]

    if (tid == 0) *rcnt = 0;
    __syncthreads();
    if (tid < 128) {
        float g1 = -FLT_MAX, g2 = -FLT_MAX; int gi = 0;
        #pragma unroll 1
        for (int j = 0; j < 16; j++) {
            float m1 = redm1[tid * 16 + j];
            float m2 = redm2[tid * 16 + j];
            int   ix = redix[tid * 16 + j];
            if (m1 > g1) { g2 = fmaxf(fmaxf(g1, m2), g2); g1 = m1; gi = ix; }
            else         { g2 = fmaxf(g2, m1); }
        }
        idx_s[tid] = gi;
        if (g1 - g2 < 2e-4f * g_norm[n0 + tid]) {
            int q = atomicAdd(rcnt, 1); rlist[q] = tid;
        }
    }
    __syncthreads();

    // ---- exact fp32 rescue for tight-margin rows ----
    const int nr = *rcnt;
    #pragma unroll 1
    for (int e = 0; e < nr; e++) {
        const int rr = rlist[e];
        const int tt = (n0 + rr) & 4095;
        if (tid < 256)
            xrow[tid] = x[((size_t)b * DIM + tid) * T_LEN + tt];
        __syncthreads();
        {
            int c = tid;          // codes tid and tid+512? K=1024, 512 threads -> 2 codes
            float dot0 = 0.f, dot1 = 0.f;
            #pragma unroll 8
            for (int d = 0; d < 256; d++) {
                float xv = xrow[d];
                dot0 = fmaf(xv, g_enT[d * K_CODES + c], dot0);
                dot1 = fmaf(xv, g_enT[d * K_CODES + c + 512], dot1);
            }
            float bv; int bi;
            if (dot0 >= dot1) { bv = dot0; bi = c; } else { bv = dot1; bi = c + 512; }
            rv[tid] = bv; rix[tid] = bi;
        }
        __syncthreads();
        if (tid == 0) {
            float best = rv[0]; int besti = rix[0];
            #pragma unroll 1
            for (int j = 1; j < NTHR; j++) {
                float v = rv[j]; int ix = rix[j];
                if (v > best || (v == best && ix < besti)) { best = v; besti = ix; }
            }
            idx_s[rr] = besti;
        }
        __syncthreads();
    }

    if (tid < 128 && out_size >= (long long)(QN + 1 + N_ROWS))
        out[QN + 1 + n0 + tid] = (float)idx_s[tid];

    // ---- gather + quantized write + exact loss (512 threads: 64 dims each) --
    const int r  = tid & 127;
    const int dq = tid >> 7;                     // quarter of D
    const int myidx = idx_s[r];
    const float4* erow4 = (const float4*)(emb + (size_t)myidx * DIM + dq * 64);
    const float* xb = x + ((size_t)b * DIM + dq * 64) * T_LEN + tl + r;
    float* ob = out + ((size_t)b * DIM + dq * 64) * T_LEN + tl + r;
    float lsum = 0.f;
    #pragma unroll 4
    for (int dj = 0; dj < 16; ++dj) {
        float4 e4 = erow4[dj];
        int d = dj * 4;
        float ev[4] = {e4.x, e4.y, e4.z, e4.w};
        #pragma unroll
        for (int i = 0; i < 4; i++) {
            float xv = xb[(size_t)(d + i) * T_LEN];
            float df = ev[i] - xv;
            lsum = fmaf(df, df, lsum);
            ob[(size_t)(d + i) * T_LEN] = ev[i];
        }
    }
    #pragma unroll
    for (int o = 16; o; o >>= 1) lsum += __shfl_xor_sync(0xFFFFFFFFu, lsum, o);
    __shared__ float wsum[16];
    if ((tid & 31) == 0) wsum[wid] = lsum;
    __syncthreads();
    if (tid == 0) {
        float t = 0.f;
        #pragma unroll
        for (int i = 0; i < 16; i++) t += wsum[i];
        if (out_size > (long long)QN)
            atomicAdd(out + QN, t * (1.25f / 16777216.0f));
    }
}

// ---------------------------------------------------------------------------
extern "C" void kernel_launch(void* const* d_in, const int* in_sizes, int n_in,
                              void* d_out, int out_size) {
    const float* x   = (const float*)d_in[0];
    const float* emb = (const float*)d_in[1];
    if (n_in >= 2 && in_sizes[0] == K_CODES * DIM && in_sizes[1] == (int)QN) {
        const float* t = x; x = emb; emb = t;
    }
    float* out = (float*)d_out;

    const int smemA = 256 * 65 * 4;                  // 66560
    const int smemM = NSTAGE * STG;                  // 110592
    cudaFuncSetAttribute(vq_prepA, cudaFuncAttributeMaxDynamicSharedMemorySize, smemA);
    cudaFuncSetAttribute(vq_main_kernel, cudaFuncAttributeMaxDynamicSharedMemorySize, smemM);

    vq_prepB<<<K_CODES, 256>>>(emb, out, (long long)out_size);
    vq_prepA<<<B_SZ * 64, 256, smemA>>>(x);
    vq_main_kernel<<<N_ROWS / 128, NTHR, smemM>>>(x, emb, out, (long long)out_size);
}